// round 9
// baseline (speedup 1.0000x reference)
#include <cuda_runtime.h>
#include <math.h>

#define LEAK 0.01f
typedef unsigned long long u64;

// ---------------- scratch (device globals; no allocation allowed) -----------
__device__ float g_seq[4096 * 180];   // [B, 18, 10] conv output / flow input
__device__ float g_fv [4096 * 10];    // [B, 10] flow vectors = [64,64,10]

// ---------------- helpers ---------------------------------------------------
__device__ __forceinline__ float lrelu(float x) { return x > 0.f ? x : LEAK * x; }

__device__ __forceinline__ float tanh_a(float x) {
    float r; asm("tanh.approx.f32 %0, %1;" : "=f"(r) : "f"(x)); return r;
}
// sigmoid(x) = (1 + tanh(x/2)) / 2
__device__ __forceinline__ float sigm(float x) {
    return fmaf(0.5f, tanh_a(0.5f * x), 0.5f);
}

// ---- packed f32x2 ops ------------------------------------------------------
__device__ __forceinline__ u64 pack2(float a, float b) {
    u64 r; asm("mov.b64 %0, {%1, %2};" : "=l"(r) : "f"(a), "f"(b)); return r;
}
__device__ __forceinline__ void unpack2(float& a, float& b, u64 v) {
    asm("mov.b64 {%0, %1}, %2;" : "=f"(a), "=f"(b) : "l"(v));
}
__device__ __forceinline__ void fma2(u64& d, u64 a, u64 b) {
    asm("fma.rn.f32x2 %0, %1, %2, %0;" : "+l"(d) : "l"(a), "l"(b));
}

// ============================================================================
// K1: conv x3 (160 threads), one block per sequence -> g_seq
// All activations stored in smem as DUPLICATED u64 {v,v}: every fma2 x-operand
// is one LDS.64 (conflict-free: stride-3 over u64, gcd(3,16)=1), zero MOVs.
// Weights co-pair packed {w_coA, w_coB}; accumulators = {out_coA, out_coB}.
// ============================================================================
__global__ __launch_bounds__(160) void conv_stage(
    const float* __restrict__ din,
    const float* __restrict__ W1, const float* __restrict__ B1,
    const float* __restrict__ W2, const float* __restrict__ B2,
    const float* __restrict__ W3, const float* __restrict__ B3)
{
    __shared__ __align__(16) u64 xsd_raw[3 * 528 + 2];   // [ci][pos], guard -1
    __shared__ __align__(16) u64 p1d_raw[10 * 176 + 2];  // [ci][pos], guard -1
    __shared__ __align__(16) u64 p2d_raw[5 * 64 + 2];    // [ci][pos], guard -1
    __shared__ u64 w1p[75];  __shared__ u64 b1p[5];      // [pr][ci*5+k]
    __shared__ u64 w2p[150]; __shared__ u64 b2p[3];      // [g][ci*5+k]
    __shared__ u64 w3p[125]; __shared__ u64 b3p[5];      // [pr][ci*5+k]

    u64* xsd = xsd_raw + 1;
    u64* p1d = p1d_raw + 1;
    u64* p2d = p2d_raw + 1;

    const int tid = threadIdx.x;
    const int b   = blockIdx.x;

    // ---- fill phase --------------------------------------------------------
    const float* xin = din + (size_t)b * 1536;
    for (int i = tid; i < 1536; i += 160) {
        const float v = xin[i];
        xsd[(i % 3) * 528 + i / 3] = pack2(v, v);
    }
    if (tid == 60) { xsd_raw[0] = 0; p1d_raw[0] = 0; p2d_raw[0] = 0; }
    for (int i = tid; i < 48; i += 160) xsd[(i / 16) * 528 + 512 + (i % 16)] = 0;
    for (int i = tid; i < 60; i += 160) p1d[(i / 6) * 176 + 170 + (i % 6)] = 0;
    for (int i = tid; i < 40; i += 160) p2d[(i / 8) * 64  + 56  + (i % 8)] = 0;
    // packed weights (co-pair)
    for (int i = tid; i < 75; i += 160) {
        const int pr = i / 15, k = i % 15;
        w1p[i] = pack2(W1[(2 * pr) * 15 + k], W1[(2 * pr + 1) * 15 + k]);
    }
    for (int i = tid; i < 150; i += 160) {
        const int g = i / 50, k = i % 50;
        const int co0 = 2 * g, co1 = (co0 + 1 < 5) ? co0 + 1 : co0;
        w2p[i] = pack2(W2[co0 * 50 + k], W2[co1 * 50 + k]);
    }
    if (tid >= 32 && tid < 157) {            // 125 loads on warps 1-4
        const int i = tid - 32;
        const int pr = i / 25, k = i % 25;
        w3p[i] = pack2(W3[(2 * pr) * 25 + k], W3[(2 * pr + 1) * 25 + k]);
    }
    if (tid < 5) b1p[tid] = pack2(B1[2 * tid], B1[2 * tid + 1]);
    if (tid < 3) b2p[tid] = pack2(B2[2 * tid], B2[(2 * tid + 1 < 5) ? 2 * tid + 1 : 2 * tid]);
    if (tid < 5) b3p[tid] = pack2(B3[2 * tid], B3[2 * tid + 1]);
    __syncthreads();

    // ---- conv1: warp = co-pair (5), lanes = j over 170 ---------------------
    {
        const int pr = tid >> 5, jb = tid & 31;
        const u64* wp = w1p + pr * 15;
        const u64  bb = b1p[pr];
        for (int j = jb; j < 170; j += 32) {
            const int c0 = 3 * j - 1;
            u64 S0 = bb, S1 = bb, S2 = bb;
            #pragma unroll
            for (int ci = 0; ci < 3; ci++) {
                u64 w[5];
                #pragma unroll
                for (int k = 0; k < 5; k++) w[k] = wp[ci * 5 + k];
                u64 xx[7];
                #pragma unroll
                for (int i = 0; i < 7; i++) xx[i] = xsd[ci * 528 + c0 + i];
                #pragma unroll
                for (int k = 0; k < 5; k++) {
                    fma2(S0, xx[k],     w[k]);
                    fma2(S1, xx[k + 1], w[k]);
                    fma2(S2, xx[k + 2], w[k]);
                }
            }
            float a0, b0, a1, b1, a2, b2;
            unpack2(a0, b0, S0); unpack2(a1, b1, S1); unpack2(a2, b2, S2);
            float ma = a1, mb = b1;
            if (j > 0)           { ma = fmaxf(ma, a0); mb = fmaxf(mb, b0); }
            if (3 * j + 1 < 508) { ma = fmaxf(ma, a2); mb = fmaxf(mb, b2); }
            const float ra = lrelu(ma), rb = lrelu(mb);
            p1d[(2 * pr) * 176 + j]     = pack2(ra, ra);
            p1d[(2 * pr + 1) * 176 + j] = pack2(rb, rb);
        }
    }
    __syncthreads();

    // ---- conv2: tasks 0..167 = (g=task/56, j=task%56) ----------------------
    {
        int task = tid;
        for (int rep = 0; rep < 2; rep++) {
            if (rep == 1) {
                if (tid >= 8) break;
                task = tid + 160;               // tasks 160..167
            }
            const int g = task / 56, j = task % 56;
            const int co0 = 2 * g;
            const int c0 = 3 * j - 1;
            u64 S0 = b2p[g], S1 = S0, S2 = S0;
            #pragma unroll
            for (int ci = 0; ci < 10; ci++) {
                u64 w[5];
                #pragma unroll
                for (int k = 0; k < 5; k++) w[k] = w2p[g * 50 + ci * 5 + k];
                u64 xx[7];
                #pragma unroll
                for (int i = 0; i < 7; i++) xx[i] = p1d[ci * 176 + c0 + i];
                #pragma unroll
                for (int k = 0; k < 5; k++) {
                    fma2(S0, xx[k],     w[k]);
                    fma2(S1, xx[k + 1], w[k]);
                    fma2(S2, xx[k + 2], w[k]);
                }
            }
            float a0, b0, a1, b1, a2, b2;
            unpack2(a0, b0, S0); unpack2(a1, b1, S1); unpack2(a2, b2, S2);
            float ma = a1, mb = b1;
            if (j > 0)           { ma = fmaxf(ma, a0); mb = fmaxf(mb, b0); }
            if (3 * j + 1 < 166) { ma = fmaxf(ma, a2); mb = fmaxf(mb, b2); }
            const float ra = lrelu(ma), rb = lrelu(mb);
            p2d[co0 * 64 + j] = pack2(ra, ra);
            if (g < 2) p2d[(co0 + 1) * 64 + j] = pack2(rb, rb);
        }
    }
    __syncthreads();

    // ---- conv3: 5 co-pairs x 18 t -> g_seq ---------------------------------
    if (tid < 90) {
        const int pr = tid / 18, t = tid % 18;
        const int c0 = 3 * t - 1;
        u64 S0 = b3p[pr], S1 = S0, S2 = S0;
        #pragma unroll
        for (int ci = 0; ci < 5; ci++) {
            u64 w[5];
            #pragma unroll
            for (int k = 0; k < 5; k++) w[k] = w3p[pr * 25 + ci * 5 + k];
            u64 xx[7];
            #pragma unroll
            for (int i = 0; i < 7; i++) xx[i] = p2d[ci * 64 + c0 + i];
            #pragma unroll
            for (int k = 0; k < 5; k++) {
                fma2(S0, xx[k],     w[k]);
                fma2(S1, xx[k + 1], w[k]);
                fma2(S2, xx[k + 2], w[k]);
            }
        }
        float a0, b0, a1, b1, a2, b2;
        unpack2(a0, b0, S0); unpack2(a1, b1, S1); unpack2(a2, b2, S2);
        float ma = a1, mb = b1;
        if (t > 0)          { ma = fmaxf(ma, a0); mb = fmaxf(mb, b0); }
        if (3 * t + 1 < 52) { ma = fmaxf(ma, a2); mb = fmaxf(mb, b2); }
        g_seq[(size_t)b * 180 + t * 10 + 2 * pr]     = lrelu(ma);
        g_seq[(size_t)b * 180 + t * 10 + 2 * pr + 1] = lrelu(mb);
    }
}

// ============================================================================
// K2: flow LSTM — one warp per sequence, 8 warps/block, zero block barriers
// ============================================================================
__global__ __launch_bounds__(256) void flow_lstm(
    const float* __restrict__ Wih, const float* __restrict__ Whh,
    const float* __restrict__ Bv)
{
    __shared__ float sA[8][184];
    __shared__ float sB[8][184];

    const int w    = threadIdx.x >> 5;
    const int lane = threadIdx.x & 31;
    const int b    = blockIdx.x * 8 + w;
    const int lhalf = lane >> 4;
    const int lu    = (lane & 15) % 10;

    for (int i = lane; i < 180; i += 32) sA[w][i] = g_seq[(size_t)b * 180 + i];
    __syncwarp();

    float acc = 0.f;
    for (int l = 0; l < 3; l++) {
        const float* wihL = Wih + l * 400;
        const float* whhL = Whh + l * 400;
        const float* bbL  = Bv  + l * 40;
        float wx[4][5], wh[4][5], bg[4];
        #pragma unroll
        for (int g = 0; g < 4; g++) {
            const int row = g * 10 + lu;
            #pragma unroll
            for (int k = 0; k < 5; k++) {
                wx[g][k] = wihL[row * 10 + lhalf * 5 + k];
                wh[g][k] = whhL[row * 10 + lhalf * 5 + k];
            }
            bg[g] = (lhalf == 0) ? bbL[row] : 0.f;
        }
        const float* inb = (l == 1) ? sB[w] : sA[w];
        float* outb      = (l == 0) ? sB[w] : sA[w];   // l==2: unused
        float c = 0.f, h = 0.f;

        float xg0, xg1, xg2, xg3;
        {
            const float* xp = inb + lhalf * 5;
            xg0 = bg[0]; xg1 = bg[1]; xg2 = bg[2]; xg3 = bg[3];
            #pragma unroll
            for (int k = 0; k < 5; k++) {
                const float xv = xp[k];
                xg0 += xv * wx[0][k]; xg1 += xv * wx[1][k];
                xg2 += xv * wx[2][k]; xg3 += xv * wx[3][k];
            }
        }
        for (int t = 0; t < 18; t++) {
            float q0 = xg0, q1 = xg1, q2 = xg2, q3 = xg3;
            #pragma unroll
            for (int k = 0; k < 5; k++) {
                const float hv = __shfl_sync(0xFFFFFFFFu, h, lhalf * 5 + k);
                q0 += hv * wh[0][k]; q1 += hv * wh[1][k];
                q2 += hv * wh[2][k]; q3 += hv * wh[3][k];
            }
            if (t + 1 < 18) {                  // prefetch next x-part
                const float* xp = inb + (t + 1) * 10 + lhalf * 5;
                xg0 = bg[0]; xg1 = bg[1]; xg2 = bg[2]; xg3 = bg[3];
                #pragma unroll
                for (int k = 0; k < 5; k++) {
                    const float xv = xp[k];
                    xg0 += xv * wx[0][k]; xg1 += xv * wx[1][k];
                    xg2 += xv * wx[2][k]; xg3 += xv * wx[3][k];
                }
            }
            q0 += __shfl_xor_sync(0xFFFFFFFFu, q0, 16);
            q1 += __shfl_xor_sync(0xFFFFFFFFu, q1, 16);
            q2 += __shfl_xor_sync(0xFFFFFFFFu, q2, 16);
            q3 += __shfl_xor_sync(0xFFFFFFFFu, q3, 16);
            const float gi = sigm(q0), gf = sigm(q1);
            const float gg = tanh_a(q2), go = sigm(q3);
            c = gf * c + gi * gg;
            h = go * tanh_a(c);
            if (l < 2 && lane < 10) outb[t * 10 + lu] = h;
            __syncwarp();
        }
        if (l >= 1) acc += h;                  // h_n[-1] + h_n[-2]
    }
    if (lane < 10) g_fv[(size_t)b * 10 + lu] = acc;
}

// ============================================================================
// K3: trace LSTM wavefront (3 warps = 3 layers, skew 1) + fused MLP head
// ============================================================================
__global__ __launch_bounds__(96) void trace_mlp(
    const float* __restrict__ Wih, const float* __restrict__ Whh,
    const float* __restrict__ Bv,
    const float* __restrict__ L1W, const float* __restrict__ L1b,
    const float* __restrict__ L2W, const float* __restrict__ L2b,
    const float* __restrict__ L3W, const float* __restrict__ L3b,
    const float* __restrict__ L4W, const float* __restrict__ L4b,
    float* __restrict__ out)
{
    __shared__ float fvb[640];        // layer-0 input
    __shared__ float sb0[640];        // layer-0 output
    __shared__ float sb1[640];        // layer-1 output
    __shared__ float tsum[2][10];
    __shared__ __align__(16) float tv[12];
    __shared__ __align__(16) float h1[128];
    __shared__ __align__(16) float h2[256];
    __shared__ __align__(16) float h3[64];

    const int tid  = threadIdx.x;
    const int wid  = tid >> 5;        // 0..2 = layer
    const int lane = tid & 31;
    const int half = lane >> 4;
    const int u    = (lane & 15) % 10;
    const int bt   = blockIdx.x;      // trace index t

    for (int i = tid; i < 640; i += 96) fvb[i] = g_fv[(size_t)bt * 640 + i];

    float wx[4][5], wh[4][5], bg[4];
    {
        const float* wihL = Wih + wid * 400;
        const float* whhL = Whh + wid * 400;
        const float* bbL  = Bv  + wid * 40;
        #pragma unroll
        for (int g = 0; g < 4; g++) {
            const int row = g * 10 + u;
            #pragma unroll
            for (int k = 0; k < 5; k++) {
                wx[g][k] = wihL[row * 10 + half * 5 + k];
                wh[g][k] = whhL[row * 10 + half * 5 + k];
            }
            bg[g] = (half == 0) ? bbL[row] : 0.f;
        }
    }
    __syncthreads();

    const float* inb = (wid == 0) ? fvb : (wid == 1) ? sb0 : sb1;
    float* outb      = (wid == 0) ? sb0 : sb1;       // wid==2 unused
    float c = 0.f, h = 0.f;

    for (int s = 0; s < 66; s++) {
        const int t = s - wid;
        if (t >= 0 && t < 64) {
            const float* xp = inb + t * 10 + half * 5;
            float q0 = bg[0], q1 = bg[1], q2 = bg[2], q3 = bg[3];
            #pragma unroll
            for (int k = 0; k < 5; k++) {
                const float xv = xp[k];
                q0 += xv * wx[0][k]; q1 += xv * wx[1][k];
                q2 += xv * wx[2][k]; q3 += xv * wx[3][k];
            }
            #pragma unroll
            for (int k = 0; k < 5; k++) {
                const float hv = __shfl_sync(0xFFFFFFFFu, h, half * 5 + k);
                q0 += hv * wh[0][k]; q1 += hv * wh[1][k];
                q2 += hv * wh[2][k]; q3 += hv * wh[3][k];
            }
            q0 += __shfl_xor_sync(0xFFFFFFFFu, q0, 16);
            q1 += __shfl_xor_sync(0xFFFFFFFFu, q1, 16);
            q2 += __shfl_xor_sync(0xFFFFFFFFu, q2, 16);
            q3 += __shfl_xor_sync(0xFFFFFFFFu, q3, 16);
            const float gi = sigm(q0), gf = sigm(q1);
            const float gg = tanh_a(q2), go = sigm(q3);
            c = gf * c + gi * gg;
            h = go * tanh_a(c);
            if (lane < 10) {
                if (wid < 2) outb[t * 10 + u] = h;
                if (t == 63 && wid >= 1) tsum[wid - 1][u] = h;
            }
        }
        __syncthreads();
    }

    if (tid < 10) tv[tid] = tsum[0][tid] + tsum[1][tid];
    __syncthreads();

    // ---- MLP head (96 threads) --------------------------------------------
    for (int o = tid; o < 128; o += 96) {
        float s = L1b[o];
        #pragma unroll
        for (int k = 0; k < 10; k++) s += tv[k] * L1W[o * 10 + k];
        h1[o] = lrelu(s);
    }
    __syncthreads();

    for (int o = tid; o < 256; o += 96) {
        const float4* wp = (const float4*)(L2W + o * 128);
        const float4* hp = (const float4*)h1;
        float sa = 0.f, sb = 0.f;
        #pragma unroll
        for (int i = 0; i < 32; i += 2) {
            const float4 w0 = wp[i],   v0 = hp[i];
            const float4 w1 = wp[i+1], v1 = hp[i+1];
            sa += w0.x*v0.x + w0.y*v0.y + w0.z*v0.z + w0.w*v0.w;
            sb += w1.x*v1.x + w1.y*v1.y + w1.z*v1.z + w1.w*v1.w;
        }
        h2[o] = lrelu(sa + sb + L2b[o]);
    }
    __syncthreads();

    if (tid < 64) {
        const float4* wp = (const float4*)(L3W + tid * 256);
        const float4* hp = (const float4*)h2;
        float sa = 0.f, sb = 0.f;
        #pragma unroll
        for (int i = 0; i < 64; i += 2) {
            const float4 w0 = wp[i],   v0 = hp[i];
            const float4 w1 = wp[i+1], v1 = hp[i+1];
            sa += w0.x*v0.x + w0.y*v0.y + w0.z*v0.z + w0.w*v0.w;
            sb += w1.x*v1.x + w1.y*v1.y + w1.z*v1.z + w1.w*v1.w;
        }
        h3[tid] = lrelu(sa + sb + L3b[tid]);
    }
    __syncthreads();

    if (tid < 7) {
        float s = L4b[tid];
        #pragma unroll
        for (int k = 0; k < 64; k++) s += h3[k] * L4W[tid * 64 + k];
        out[bt * 7 + tid] = s;
    }
}

// ---------------- launch ----------------------------------------------------
extern "C" void kernel_launch(void* const* d_in, const int* in_sizes, int n_in,
                              void* d_out, int out_size)
{
    const float* din  = (const float*)d_in[0];
    const float* W1   = (const float*)d_in[1];
    const float* b1   = (const float*)d_in[2];
    const float* W2   = (const float*)d_in[3];
    const float* b2   = (const float*)d_in[4];
    const float* W3   = (const float*)d_in[5];
    const float* b3   = (const float*)d_in[6];
    const float* fWih = (const float*)d_in[7];
    const float* fWhh = (const float*)d_in[8];
    const float* fb   = (const float*)d_in[9];
    const float* tWih = (const float*)d_in[10];
    const float* tWhh = (const float*)d_in[11];
    const float* tb   = (const float*)d_in[12];
    const float* L1W  = (const float*)d_in[13];
    const float* L1b  = (const float*)d_in[14];
    const float* L2W  = (const float*)d_in[15];
    const float* L2b  = (const float*)d_in[16];
    const float* L3W  = (const float*)d_in[17];
    const float* L3b  = (const float*)d_in[18];
    const float* L4W  = (const float*)d_in[19];
    const float* L4b  = (const float*)d_in[20];

    conv_stage<<<4096, 160>>>(din, W1, b1, W2, b2, W3, b3);
    flow_lstm <<<512, 256>>>(fWih, fWhh, fb);
    trace_mlp <<<64, 96>>>(tWih, tWhh, tb,
                           L1W, L1b, L2W, L2b, L3W, L3b, L4W, L4b,
                           (float*)d_out);
}

// round 10
// speedup vs baseline: 1.1742x; 1.1742x over previous
#include <cuda_runtime.h>
#include <math.h>

#define LEAK 0.01f
typedef unsigned long long u64;

// ---------------- scratch (device globals; no allocation allowed) -----------
__device__ float g_seq[4096 * 180];   // [B, 18, 10] conv output / flow input
__device__ float g_fv [4096 * 10];    // [B, 10] flow vectors = [64,64,10]

// ---------------- helpers ---------------------------------------------------
__device__ __forceinline__ float lrelu(float x) { return x > 0.f ? x : LEAK * x; }

__device__ __forceinline__ float tanh_a(float x) {
    float r; asm("tanh.approx.f32 %0, %1;" : "=f"(r) : "f"(x)); return r;
}
// sigmoid(x) = (1 + tanh(x/2)) / 2
__device__ __forceinline__ float sigm(float x) {
    return fmaf(0.5f, tanh_a(0.5f * x), 0.5f);
}

// ---- packed f32x2 ops ------------------------------------------------------
__device__ __forceinline__ u64 pack2(float a, float b) {
    u64 r; asm("mov.b64 %0, {%1, %2};" : "=l"(r) : "f"(a), "f"(b)); return r;
}
__device__ __forceinline__ void unpack2(float& a, float& b, u64 v) {
    asm("mov.b64 {%0, %1}, %2;" : "=f"(a), "=f"(b) : "l"(v));
}
__device__ __forceinline__ void fma2(u64& d, u64 a, u64 b) {
    asm("fma.rn.f32x2 %0, %1, %2, %0;" : "+l"(d) : "l"(a), "l"(b));
}

// branch-free fused conv(K=5)+pool3(pad1)+lrelu for a packed channel pair.
// xs points one past a zero guard (index -1 valid & zero); rows padded w/ zeros.
template<int CIN, int STRIDE, int VALIDL>
__device__ __forceinline__ void conv_pool2(const float* __restrict__ xs,
                                           const u64* __restrict__ wp,
                                           u64 bb, int j,
                                           float& ra, float& rb)
{
    const int c0 = 3 * j - 1;
    u64 S0 = bb, S1 = bb, S2 = bb;
    #pragma unroll
    for (int ci = 0; ci < CIN; ci++) {
        u64 w[5];
        #pragma unroll
        for (int k = 0; k < 5; k++) w[k] = wp[ci * 5 + k];
        u64 xx[7];
        #pragma unroll
        for (int i = 0; i < 7; i++) {
            const float v = xs[ci * STRIDE + c0 + i];
            xx[i] = pack2(v, v);
        }
        #pragma unroll
        for (int k = 0; k < 5; k++) {
            fma2(S0, xx[k],     w[k]);
            fma2(S1, xx[k + 1], w[k]);
            fma2(S2, xx[k + 2], w[k]);
        }
    }
    float a0, b0, a1, b1, a2, b2;
    unpack2(a0, b0, S0); unpack2(a1, b1, S1); unpack2(a2, b2, S2);
    float ma = a1, mb = b1;                    // center (l=3j) always valid
    if (j > 0)              { ma = fmaxf(ma, a0); mb = fmaxf(mb, b0); }
    if (3 * j + 1 < VALIDL) { ma = fmaxf(ma, a2); mb = fmaxf(mb, b2); }
    ra = lrelu(ma); rb = lrelu(mb);
}

// ============================================================================
// K1: conv x3 only (5 warps), one block per sequence -> g_seq
// (exact best-measured configuration: 49.4us profile / 96.6us total)
// ============================================================================
__global__ __launch_bounds__(160) void conv_stage(
    const float* __restrict__ din,
    const float* __restrict__ W1, const float* __restrict__ B1,
    const float* __restrict__ W2, const float* __restrict__ B2,
    const float* __restrict__ W3, const float* __restrict__ B3)
{
    __shared__ float xs_raw[3 * 520 + 4];     // stride 520, +1 front guard
    __shared__ float p1_raw[10 * 176 + 4];    // stride 176
    __shared__ float p2_raw[5 * 64 + 4];      // stride 64
    __shared__ u64  w1p[75];  __shared__ u64 b1p[5];
    __shared__ u64  w2p[150]; __shared__ u64 b2p[3];
    __shared__ u64  w3p[125]; __shared__ u64 b3p[5];

    float* xs = xs_raw + 1;
    float* p1 = p1_raw + 1;
    float* p2 = p2_raw + 1;

    const int tid = threadIdx.x;
    const int b   = blockIdx.x;

    // ---- fill phase --------------------------------------------------------
    const float* xin = din + (size_t)b * 1536;
    for (int i = tid; i < 1536; i += 160) xs[(i % 3) * 520 + i / 3] = xin[i];
    // zero guards + row pads
    if (tid == 60) { xs_raw[0] = 0.f; p1_raw[0] = 0.f; p2_raw[0] = 0.f; }
    for (int i = tid; i < 24; i += 160) xs[(i / 8) * 520 + 512 + (i % 8)] = 0.f;
    for (int i = tid; i < 60; i += 160) p1[(i / 6) * 176 + 170 + (i % 6)] = 0.f;
    for (int i = tid; i < 40; i += 160) p2[(i / 8) * 64  + 56  + (i % 8)] = 0.f;
    // packed weights
    for (int i = tid; i < 75; i += 160) {
        const int pr = i / 15, k = i % 15;
        w1p[i] = pack2(W1[(2 * pr) * 15 + k], W1[(2 * pr + 1) * 15 + k]);
    }
    for (int i = tid; i < 150; i += 160) {
        const int g = i / 50, k = i % 50;
        const int co0 = 2 * g, co1 = (co0 + 1 < 5) ? co0 + 1 : co0;
        w2p[i] = pack2(W2[co0 * 50 + k], W2[co1 * 50 + k]);
    }
    if (tid >= 32 && tid < 157) {             // 125 loads on warps 1-4
        const int i = tid - 32;
        const int pr = i / 25, k = i % 25;
        w3p[i] = pack2(W3[(2 * pr) * 25 + k], W3[(2 * pr + 1) * 25 + k]);
    }
    if (tid < 5) b1p[tid] = pack2(B1[2 * tid], B1[2 * tid + 1]);
    if (tid < 3) b2p[tid] = pack2(B2[2 * tid], B2[(2 * tid + 1 < 5) ? 2 * tid + 1 : 2 * tid]);
    if (tid < 5) b3p[tid] = pack2(B3[2 * tid], B3[2 * tid + 1]);
    __syncthreads();

    // ---- conv1: 5 pairs x 32 lanes over 170 j ------------------------------
    {
        const int pr = tid >> 5, jb = tid & 31;
        const u64* wp = w1p + pr * 15;
        const u64  bb = b1p[pr];
        for (int j = jb; j < 170; j += 32) {
            float ra, rb;
            conv_pool2<3, 520, 508>(xs, wp, bb, j, ra, rb);
            p1[(2 * pr) * 176 + j]     = ra;
            p1[(2 * pr + 1) * 176 + j] = rb;
        }
    }
    __syncthreads();

    // ---- conv2: tasks 0..167 = (g=task/56, j=task%56) ----------------------
    {
        int task = tid;
        for (int rep = 0; rep < 2; rep++) {
            if (rep == 1) {
                if (tid >= 8) break;
                task = tid + 160;               // tasks 160..167
            }
            const int g = task / 56, j = task % 56;
            const int co0 = 2 * g;
            float ra, rb;
            conv_pool2<10, 176, 166>(p1, w2p + g * 50, b2p[g], j, ra, rb);
            p2[co0 * 64 + j] = ra;
            if (g < 2) p2[(co0 + 1) * 64 + j] = rb;
        }
    }
    __syncthreads();

    // ---- conv3: 5 co-pairs x 18 t -> g_seq ---------------------------------
    if (tid < 90) {
        const int pr = tid / 18, t = tid % 18;
        float ra, rb;
        conv_pool2<5, 64, 52>(p2, w3p + pr * 25, b3p[pr], t, ra, rb);
        g_seq[(size_t)b * 180 + t * 10 + 2 * pr]     = ra;
        g_seq[(size_t)b * 180 + t * 10 + 2 * pr + 1] = rb;
    }
}

// ============================================================================
// K2: flow LSTM — TWO sequences per warp (half-warp each, full k per lane),
// 8 warps/block = 16 seqs, zero block barriers, zero reduction shfls.
// lane = s*16 + u  (s = seq-in-warp, u = hidden unit, u<10 active)
// ============================================================================
__global__ __launch_bounds__(256) void flow_lstm(
    const float* __restrict__ Wih, const float* __restrict__ Whh,
    const float* __restrict__ Bv)
{
    __shared__ float sA[16][184];
    __shared__ float sB[16][184];

    const int w    = threadIdx.x >> 5;
    const int lane = threadIdx.x & 31;
    const int s    = lane >> 4;            // 0/1
    const int u    = lane & 15;            // unit (0..9 active)
    const int uu   = (u < 10) ? u : 9;     // clamp for safe weight loads
    const int seq  = w * 2 + s;
    const int b    = blockIdx.x * 16 + seq;
    const int srcb = s * 16;               // shfl source base for this seq

    // warp loads its two sequences
    {
        const int s0 = w * 2;
        for (int i = lane; i < 360; i += 32) {
            const int ss = i / 180, off = i % 180;
            sA[s0 + ss][off] =
                g_seq[(size_t)(blockIdx.x * 16 + s0 + ss) * 180 + off];
        }
    }
    __syncwarp();

    float acc = 0.f;
    for (int l = 0; l < 3; l++) {
        const float* wihL = Wih + l * 400;
        const float* whhL = Whh + l * 400;
        const float* bbL  = Bv  + l * 40;
        float wx[4][10], wh[4][10], bg[4];
        #pragma unroll
        for (int g = 0; g < 4; g++) {
            const int row = g * 10 + uu;
            #pragma unroll
            for (int k = 0; k < 10; k++) {
                wx[g][k] = wihL[row * 10 + k];
                wh[g][k] = whhL[row * 10 + k];
            }
            bg[g] = bbL[row];
        }
        const float* inb = (l == 1) ? sB[seq] : sA[seq];
        float* outb      = (l == 0) ? sB[seq] : sA[seq];   // l==2: unused
        float c = 0.f, h = 0.f;

        // prefetch x-part for t=0
        float xg0, xg1, xg2, xg3;
        {
            const float* xp = inb;
            xg0 = bg[0]; xg1 = bg[1]; xg2 = bg[2]; xg3 = bg[3];
            #pragma unroll
            for (int k = 0; k < 10; k++) {
                const float xv = xp[k];
                xg0 += xv * wx[0][k]; xg1 += xv * wx[1][k];
                xg2 += xv * wx[2][k]; xg3 += xv * wx[3][k];
            }
        }
        for (int t = 0; t < 18; t++) {
            float q0 = xg0, q1 = xg1, q2 = xg2, q3 = xg3;
            #pragma unroll
            for (int k = 0; k < 10; k++) {
                const float hv = __shfl_sync(0xFFFFFFFFu, h, srcb + k);
                q0 += hv * wh[0][k]; q1 += hv * wh[1][k];
                q2 += hv * wh[2][k]; q3 += hv * wh[3][k];
            }
            if (t + 1 < 18) {                  // prefetch next x-part
                const float* xp = inb + (t + 1) * 10;
                xg0 = bg[0]; xg1 = bg[1]; xg2 = bg[2]; xg3 = bg[3];
                #pragma unroll
                for (int k = 0; k < 10; k++) {
                    const float xv = xp[k];
                    xg0 += xv * wx[0][k]; xg1 += xv * wx[1][k];
                    xg2 += xv * wx[2][k]; xg3 += xv * wx[3][k];
                }
            }
            const float gi = sigm(q0), gf = sigm(q1);
            const float gg = tanh_a(q2), go = sigm(q3);
            c = gf * c + gi * gg;
            h = go * tanh_a(c);
            if (l < 2 && u < 10) outb[t * 10 + u] = h;
            __syncwarp();
        }
        if (l >= 1) acc += h;                  // h_n[-1] + h_n[-2]
    }
    if (u < 10) g_fv[(size_t)b * 10 + u] = acc;
}

// ============================================================================
// K3: trace LSTM wavefront (warps 0-2 = layers, skew 1) + MLP on 128 threads
// ============================================================================
__global__ __launch_bounds__(128) void trace_mlp(
    const float* __restrict__ Wih, const float* __restrict__ Whh,
    const float* __restrict__ Bv,
    const float* __restrict__ L1W, const float* __restrict__ L1b,
    const float* __restrict__ L2W, const float* __restrict__ L2b,
    const float* __restrict__ L3W, const float* __restrict__ L3b,
    const float* __restrict__ L4W, const float* __restrict__ L4b,
    float* __restrict__ out)
{
    __shared__ float fvb[640];        // layer-0 input
    __shared__ float sb0[640];        // layer-0 output
    __shared__ float sb1[640];        // layer-1 output
    __shared__ float tsum[2][10];
    __shared__ __align__(16) float tv[12];
    __shared__ __align__(16) float h1[128];
    __shared__ __align__(16) float h2[256];
    __shared__ __align__(16) float h3[64];

    const int tid  = threadIdx.x;
    const int wid  = tid >> 5;        // 0..2 = layer, 3 = helper
    const int lane = tid & 31;
    const int half = lane >> 4;
    const int u    = (lane & 15) % 10;
    const int bt   = blockIdx.x;      // trace index t

    for (int i = tid; i < 640; i += 128) fvb[i] = g_fv[(size_t)bt * 640 + i];

    float wx[4][5], wh[4][5], bg[4];
    if (wid < 3) {
        const float* wihL = Wih + wid * 400;
        const float* whhL = Whh + wid * 400;
        const float* bbL  = Bv  + wid * 40;
        #pragma unroll
        for (int g = 0; g < 4; g++) {
            const int row = g * 10 + u;
            #pragma unroll
            for (int k = 0; k < 5; k++) {
                wx[g][k] = wihL[row * 10 + half * 5 + k];
                wh[g][k] = whhL[row * 10 + half * 5 + k];
            }
            bg[g] = (half == 0) ? bbL[row] : 0.f;
        }
    }
    __syncthreads();

    const float* inb = (wid == 0) ? fvb : (wid == 1) ? sb0 : sb1;
    float* outb      = (wid == 0) ? sb0 : sb1;       // wid>=2 unused
    float c = 0.f, h = 0.f;

    for (int s = 0; s < 66; s++) {
        const int t = s - wid;
        if (wid < 3 && t >= 0 && t < 64) {
            const float* xp = inb + t * 10 + half * 5;
            float q0 = bg[0], q1 = bg[1], q2 = bg[2], q3 = bg[3];
            #pragma unroll
            for (int k = 0; k < 5; k++) {
                const float xv = xp[k];
                q0 += xv * wx[0][k]; q1 += xv * wx[1][k];
                q2 += xv * wx[2][k]; q3 += xv * wx[3][k];
            }
            #pragma unroll
            for (int k = 0; k < 5; k++) {
                const float hv = __shfl_sync(0xFFFFFFFFu, h, half * 5 + k);
                q0 += hv * wh[0][k]; q1 += hv * wh[1][k];
                q2 += hv * wh[2][k]; q3 += hv * wh[3][k];
            }
            q0 += __shfl_xor_sync(0xFFFFFFFFu, q0, 16);
            q1 += __shfl_xor_sync(0xFFFFFFFFu, q1, 16);
            q2 += __shfl_xor_sync(0xFFFFFFFFu, q2, 16);
            q3 += __shfl_xor_sync(0xFFFFFFFFu, q3, 16);
            const float gi = sigm(q0), gf = sigm(q1);
            const float gg = tanh_a(q2), go = sigm(q3);
            c = gf * c + gi * gg;
            h = go * tanh_a(c);
            if (lane < 10) {
                if (wid < 2) outb[t * 10 + u] = h;
                if (t == 63 && wid >= 1) tsum[wid - 1][u] = h;
            }
        }
        __syncthreads();
    }

    if (tid < 10) tv[tid] = tsum[0][tid] + tsum[1][tid];
    __syncthreads();

    // ---- MLP head (128 threads) ---------------------------------------
    {
        float ss = L1b[tid];
        #pragma unroll
        for (int k = 0; k < 10; k++) ss += tv[k] * L1W[tid * 10 + k];
        h1[tid] = lrelu(ss);
    }
    __syncthreads();

    for (int o = tid; o < 256; o += 128) {
        const float4* wp = (const float4*)(L2W + o * 128);
        const float4* hp = (const float4*)h1;
        float sa = 0.f, sb = 0.f;
        #pragma unroll
        for (int i = 0; i < 32; i += 2) {
            const float4 w0 = wp[i],   v0 = hp[i];
            const float4 w1 = wp[i+1], v1 = hp[i+1];
            sa += w0.x*v0.x + w0.y*v0.y + w0.z*v0.z + w0.w*v0.w;
            sb += w1.x*v1.x + w1.y*v1.y + w1.z*v1.z + w1.w*v1.w;
        }
        h2[o] = lrelu(sa + sb + L2b[o]);
    }
    __syncthreads();

    if (tid < 64) {
        const float4* wp = (const float4*)(L3W + tid * 256);
        const float4* hp = (const float4*)h2;
        float sa = 0.f, sb = 0.f;
        #pragma unroll
        for (int i = 0; i < 64; i += 2) {
            const float4 w0 = wp[i],   v0 = hp[i];
            const float4 w1 = wp[i+1], v1 = hp[i+1];
            sa += w0.x*v0.x + w0.y*v0.y + w0.z*v0.z + w0.w*v0.w;
            sb += w1.x*v1.x + w1.y*v1.y + w1.z*v1.z + w1.w*v1.w;
        }
        h3[tid] = lrelu(sa + sb + L3b[tid]);
    }
    __syncthreads();

    if (tid < 7) {
        float ss = L4b[tid];
        #pragma unroll
        for (int k = 0; k < 64; k++) ss += h3[k] * L4W[tid * 64 + k];
        out[bt * 7 + tid] = ss;
    }
}

// ---------------- launch ----------------------------------------------------
extern "C" void kernel_launch(void* const* d_in, const int* in_sizes, int n_in,
                              void* d_out, int out_size)
{
    const float* din  = (const float*)d_in[0];
    const float* W1   = (const float*)d_in[1];
    const float* b1   = (const float*)d_in[2];
    const float* W2   = (const float*)d_in[3];
    const float* b2   = (const float*)d_in[4];
    const float* W3   = (const float*)d_in[5];
    const float* b3   = (const float*)d_in[6];
    const float* fWih = (const float*)d_in[7];
    const float* fWhh = (const float*)d_in[8];
    const float* fb   = (const float*)d_in[9];
    const float* tWih = (const float*)d_in[10];
    const float* tWhh = (const float*)d_in[11];
    const float* tb   = (const float*)d_in[12];
    const float* L1W  = (const float*)d_in[13];
    const float* L1b  = (const float*)d_in[14];
    const float* L2W  = (const float*)d_in[15];
    const float* L2b  = (const float*)d_in[16];
    const float* L3W  = (const float*)d_in[17];
    const float* L3b  = (const float*)d_in[18];
    const float* L4W  = (const float*)d_in[19];
    const float* L4b  = (const float*)d_in[20];

    conv_stage<<<4096, 160>>>(din, W1, b1, W2, b2, W3, b3);
    flow_lstm <<<256, 256>>>(fWih, fWhh, fb);
    trace_mlp <<<64, 128>>>(tWih, tWhh, tb,
                            L1W, L1b, L2W, L2b, L3W, L3b, L4W, L4b,
                            (float*)d_out);
}